// round 16
// baseline (speedup 1.0000x reference)
#include <cuda_runtime.h>
#include <cuda_bf16.h>
#include <mma.h>
#include <math.h>

using namespace nvcuda;

#define NNODES 100000
#define NEDGES 1600000
#define DHID 128
#define DOUT 64
#define BN_EPS 1e-5f
#define NB ((NNODES + 255) / 256)
#define LDS_ 136   // smem row stride (bf16 elems) for 128-wide tiles

// buffer selectors
#define SEL_ARG 0
#define SEL_AGG 1
#define SEL_PRE 2

// ---------------- scratch (static device globals; no allocation) -------------
__device__ __align__(16) float g_agg[NNODES * DHID];
__device__ __align__(16) float g_pre[NNODES * DHID];
__device__ int   g_rowptr[NNODES + 1];
__device__ int   g_cursor[NNODES];
__device__ int   g_bsum[NB];
__device__ int   g_boff[NB];
__device__ int   g_srcs[NEDGES];
__device__ __align__(16) float g_wts [NEDGES];
__device__ float g_stats[2 * DHID];
__device__ __align__(16) float g_scale[DHID];
__device__ __align__(16) float g_shift[DHID];
__device__ int   g_is64;

__device__ __forceinline__ const float* sel_cbuf(int sel, const float* arg) {
    switch (sel) {
        case SEL_AGG: return g_agg;
        case SEL_PRE: return g_pre;
        default:      return arg;
    }
}
__device__ __forceinline__ float* sel_mbuf(int sel, float* arg) {
    switch (sel) {
        case SEL_AGG: return g_agg;
        case SEL_PRE: return g_pre;
        default:      return arg;
    }
}

__device__ __forceinline__ int fetch_src(const int* ei32, int e, int is64) {
    return is64 ? ei32[2 * e] : ei32[e];
}
__device__ __forceinline__ int fetch_dst(const int* ei32, int e, int is64) {
    return is64 ? ei32[2 * (NEDGES + e)] : ei32[NEDGES + e];
}

// split a float4 into bf16 hi/lo, packed stores
__device__ __forceinline__ void split_store4(__nv_bfloat16* hip,
                                             __nv_bfloat16* lop, float4 v) {
    float f[4] = {v.x, v.y, v.z, v.w};
    __nv_bfloat16 h[4], l[4];
    #pragma unroll
    for (int j = 0; j < 4; j++) {
        h[j] = __float2bfloat16(f[j]);
        l[j] = __float2bfloat16(f[j] - __bfloat162float(h[j]));
    }
    ((__nv_bfloat162*)hip)[0] = __nv_bfloat162(h[0], h[1]);
    ((__nv_bfloat162*)hip)[1] = __nv_bfloat162(h[2], h[3]);
    ((__nv_bfloat162*)lop)[0] = __nv_bfloat162(l[0], l[1]);
    ((__nv_bfloat162*)lop)[1] = __nv_bfloat162(l[2], l[3]);
}

// ---------------- dtype detection --------------------------------------------
__global__ void detect_dtype_kernel(const int* __restrict__ ei32) {
    __shared__ int s_nonzero;
    if (threadIdx.x == 0) s_nonzero = 0;
    __syncthreads();
    for (int k = threadIdx.x; k < 4096; k += blockDim.x) {
        if (ei32[2 * k + 1] != 0) atomicOr(&s_nonzero, 1);
    }
    __syncthreads();
    if (threadIdx.x == 0) g_is64 = s_nonzero ? 0 : 1;
}

// ---------------- small utility kernels --------------------------------------
__global__ void zero_cursor_kernel() {
    int i = blockIdx.x * blockDim.x + threadIdx.x;
    if (i < NNODES) g_cursor[i] = 0;
}
__global__ void zero_stats_kernel() {
    int i = threadIdx.x;
    if (i < 2 * DHID) g_stats[i] = 0.0f;
}

// ---------------- CSR build ---------------------------------------------------
__global__ void hist_kernel(const int* __restrict__ ei32) {
    int e = blockIdx.x * blockDim.x + threadIdx.x;
    if (e < NEDGES) {
        int d = fetch_dst(ei32, e, g_is64);
        atomicAdd(&g_cursor[d], 1);
    }
}

__global__ void block_reduce_kernel() {
    __shared__ int ws[8];
    int tid = threadIdx.x, lane = tid & 31, wid = tid >> 5;
    int i = blockIdx.x * 256 + tid;
    int v = (i < NNODES) ? g_cursor[i] : 0;
    #pragma unroll
    for (int d = 16; d > 0; d >>= 1) v += __shfl_down_sync(0xFFFFFFFFu, v, d);
    if (lane == 0) ws[wid] = v;
    __syncthreads();
    if (wid == 0) {
        int s = (lane < 8) ? ws[lane] : 0;
        #pragma unroll
        for (int d = 4; d > 0; d >>= 1) s += __shfl_down_sync(0xFFFFFFFFu, s, d);
        if (lane == 0) g_bsum[blockIdx.x] = s;
    }
}

__global__ void scan_bsums_kernel() {
    __shared__ int wsum[16];
    int tid = threadIdx.x, lane = tid & 31, wid = tid >> 5;
    int v = (tid < NB) ? g_bsum[tid] : 0;
    int x = v;
    #pragma unroll
    for (int d = 1; d < 32; d <<= 1) {
        int y = __shfl_up_sync(0xFFFFFFFFu, x, d);
        if (lane >= d) x += y;
    }
    if (lane == 31) wsum[wid] = x;
    __syncthreads();
    if (wid == 0) {
        int s = (lane < 16) ? wsum[lane] : 0;
        #pragma unroll
        for (int d = 1; d < 16; d <<= 1) {
            int y = __shfl_up_sync(0xFFFFFFFFu, s, d);
            if (lane >= d) s += y;
        }
        if (lane < 16) wsum[lane] = s;
    }
    __syncthreads();
    int incl = x + (wid > 0 ? wsum[wid - 1] : 0);
    if (tid < NB) g_boff[tid] = incl - v;
    if (tid == NB - 1) g_rowptr[NNODES] = incl;
}

__global__ void block_scan_kernel() {
    __shared__ int ws[8];
    int tid = threadIdx.x, lane = tid & 31, wid = tid >> 5;
    int i = blockIdx.x * 256 + tid;
    int v = (i < NNODES) ? g_cursor[i] : 0;
    int x = v;
    #pragma unroll
    for (int d = 1; d < 32; d <<= 1) {
        int y = __shfl_up_sync(0xFFFFFFFFu, x, d);
        if (lane >= d) x += y;
    }
    if (lane == 31) ws[wid] = x;
    __syncthreads();
    if (wid == 0 && lane < 8) {
        int s = ws[lane];
        #pragma unroll
        for (int d = 1; d < 8; d <<= 1) {
            int y = __shfl_up_sync(0x000000FFu, s, d);
            if (lane >= d) s += y;
        }
        ws[lane] = s;
    }
    __syncthreads();
    int excl = x - v + (wid > 0 ? ws[wid - 1] : 0) + g_boff[blockIdx.x];
    if (i < NNODES) { g_rowptr[i] = excl; g_cursor[i] = excl; }
}

__global__ void scatter_kernel(const int* __restrict__ ei32,
                               const float* __restrict__ ew) {
    int e = blockIdx.x * blockDim.x + threadIdx.x;
    if (e < NEDGES) {
        int is64 = g_is64;
        int s = fetch_src(ei32, e, is64);
        int d = fetch_dst(ei32, e, is64);
        float w = ew[e];
        int pos = atomicAdd(&g_cursor[d], 1);
        g_srcs[pos] = s;
        g_wts [pos] = w;
    }
}

// ---------------- propagate (128-dim): warp-per-node gather -> g_agg ----------
template <bool BN>
__global__ void propagate_kernel(int hsel, const float* __restrict__ harg) {
    const float* __restrict__ h = BN ? g_pre : sel_cbuf(hsel, harg);
    int warp = (blockIdx.x * blockDim.x + threadIdx.x) >> 5;
    int lane = threadIdx.x & 31;
    if (warp >= NNODES) return;
    float4 sc, sh;
    if (BN) {
        sc = ((const float4*)g_scale)[lane];
        sh = ((const float4*)g_shift)[lane];
    }
    int beg = g_rowptr[warp];
    int end = g_rowptr[warp + 1];
    float4 acc = make_float4(0.f, 0.f, 0.f, 0.f);
    for (int e = beg; e < end; e++) {
        int   s = g_srcs[e];
        float w = g_wts[e];
        float4 v = *((const float4*)(h + (size_t)s * DHID) + lane);
        if (BN) {
            v.x = fmaxf(v.x * sc.x + sh.x, 0.f);
            v.y = fmaxf(v.y * sc.y + sh.y, 0.f);
            v.z = fmaxf(v.z * sc.z + sh.z, 0.f);
            v.w = fmaxf(v.w * sc.w + sh.w, 0.f);
        }
        acc.x += w * v.x; acc.y += w * v.y;
        acc.z += w * v.z; acc.w += w * v.w;
    }
    ((float4*)(g_agg + (size_t)warp * DHID))[lane] = acc;
}

// ---------------- propagate (64-dim) + bias: logits path ----------------------
// out = sum_e w_e * g_agg[src_e] + b3  (g_agg holds out_h @ W3.T, 64-stride)
__global__ void propagate64_bias_kernel(const float* __restrict__ bias,
                                        float* __restrict__ out) {
    int warp = (blockIdx.x * blockDim.x + threadIdx.x) >> 5;
    int lane = threadIdx.x & 31;
    if (warp >= NNODES) return;
    int beg = g_rowptr[warp];
    int end = g_rowptr[warp + 1];
    float2 acc = make_float2(0.f, 0.f);
    for (int e = beg; e < end; e++) {
        int   s = g_srcs[e];
        float w = g_wts[e];
        float2 v = *((const float2*)(g_agg + (size_t)s * DOUT) + lane);
        acc.x += w * v.x; acc.y += w * v.y;
    }
    float2 b = ((const float2*)bias)[lane];
    acc.x += b.x; acc.y += b.y;
    ((float2*)(out + (size_t)warp * DOUT))[lane] = acc;
}

// ---------------- tensor-core GEMM: fully smem-resident K ---------------------
// C[N,NC] = A[N,128] @ W[NC,128]^T (+bias) (+relu)
template <int NC, bool RELU, bool BIAS>
__launch_bounds__(256)
__global__ void gemm_wmma_kernel(int asel, const float* __restrict__ Aarg,
                                 const float* __restrict__ W,
                                 const float* __restrict__ bias,
                                 int csel, float* __restrict__ Carg) {
    constexpr int BM = 128, K = 128;
    constexpr int NF = NC / 32;
    const float* __restrict__ A = sel_cbuf(asel, Aarg);
    float* __restrict__ C = sel_mbuf(csel, Carg);

    extern __shared__ __align__(16) char dsm[];
    __nv_bfloat16* sAh = (__nv_bfloat16*)dsm;           // [BM][LDS_]
    __nv_bfloat16* sAl = sAh + BM * LDS_;
    __nv_bfloat16* sWh = sAl + BM * LDS_;               // [NC][LDS_]
    __nv_bfloat16* sWl = sWh + NC * LDS_;
    float* Cs = (float*)dsm;                            // epilogue overlay

    int tid  = threadIdx.x;
    int row0 = blockIdx.x * BM;

    #pragma unroll
    for (int i = tid; i < BM * (K / 4); i += 256) {
        int r = i / (K / 4), c4 = (i % (K / 4)) * 4;
        int gr = row0 + r;
        float4 v = (gr < NNODES)
            ? *(const float4*)(A + (size_t)gr * K + c4)
            : make_float4(0.f, 0.f, 0.f, 0.f);
        split_store4(sAh + r * LDS_ + c4, sAl + r * LDS_ + c4, v);
    }
    #pragma unroll
    for (int i = tid; i < NC * (K / 4); i += 256) {
        int r = i / (K / 4), c4 = (i % (K / 4)) * 4;
        float4 v = *(const float4*)(W + (size_t)r * K + c4);
        split_store4(sWh + r * LDS_ + c4, sWl + r * LDS_ + c4, v);
    }
    __syncthreads();

    int wid = tid >> 5;
    int wr  = wid >> 1;
    int wc  = wid & 1;

    wmma::fragment<wmma::accumulator, 16, 16, 16, float> acc[2][NF];
    #pragma unroll
    for (int m = 0; m < 2; m++)
        #pragma unroll
        for (int n = 0; n < NF; n++) wmma::fill_fragment(acc[m][n], 0.f);

    #pragma unroll
    for (int k0 = 0; k0 < K; k0 += 16) {
        wmma::fragment<wmma::matrix_a, 16, 16, 16, __nv_bfloat16, wmma::row_major> ah[2], al[2];
        wmma::fragment<wmma::matrix_b, 16, 16, 16, __nv_bfloat16, wmma::col_major> bh[NF], bl[NF];
        #pragma unroll
        for (int m = 0; m < 2; m++) {
            int r = wr * 32 + m * 16;
            wmma::load_matrix_sync(ah[m], sAh + r * LDS_ + k0, LDS_);
            wmma::load_matrix_sync(al[m], sAl + r * LDS_ + k0, LDS_);
        }
        #pragma unroll
        for (int n = 0; n < NF; n++) {
            int c = wc * (NC / 2) + n * 16;
            wmma::load_matrix_sync(bh[n], sWh + c * LDS_ + k0, LDS_);
            wmma::load_matrix_sync(bl[n], sWl + c * LDS_ + k0, LDS_);
        }
        #pragma unroll
        for (int m = 0; m < 2; m++)
            #pragma unroll
            for (int n = 0; n < NF; n++) {
                wmma::mma_sync(acc[m][n], ah[m], bh[n], acc[m][n]);
                wmma::mma_sync(acc[m][n], ah[m], bl[n], acc[m][n]);
                wmma::mma_sync(acc[m][n], al[m], bh[n], acc[m][n]);
            }
    }

    __syncthreads();
    #pragma unroll
    for (int m = 0; m < 2; m++)
        #pragma unroll
        for (int n = 0; n < NF; n++)
            wmma::store_matrix_sync(
                Cs + (wr * 32 + m * 16) * NC + wc * (NC / 2) + n * 16,
                acc[m][n], NC, wmma::mem_row_major);
    __syncthreads();
    #pragma unroll
    for (int i = tid; i < BM * (NC / 4); i += 256) {
        int r = i / (NC / 4), c4 = (i % (NC / 4)) * 4;
        int gr = row0 + r;
        if (gr < NNODES) {
            float4 v = *(float4*)(Cs + r * NC + c4);
            float4 o = v;
            if (BIAS) {
                float4 b = *(const float4*)(bias + c4);
                o.x += b.x; o.y += b.y; o.z += b.z; o.w += b.w;
            }
            if (RELU) {
                o.x = fmaxf(o.x, 0.f); o.y = fmaxf(o.y, 0.f);
                o.z = fmaxf(o.z, 0.f); o.w = fmaxf(o.w, 0.f);
            }
            *(float4*)(C + (size_t)gr * NC + c4) = o;
        }
    }
}

// ---------------- BatchNorm (stats over g_pre) --------------------------------
__global__ void bn_stats_kernel() {
    int c = threadIdx.x;
    float s = 0.f, sq = 0.f;
    for (int r = blockIdx.x; r < NNODES; r += gridDim.x) {
        float v = g_pre[(size_t)r * DHID + c];
        s += v; sq += v * v;
    }
    atomicAdd(&g_stats[c], s);
    atomicAdd(&g_stats[DHID + c], sq);
}

__global__ void bn_finalize_kernel(const float* __restrict__ g,
                                   const float* __restrict__ be) {
    int c = threadIdx.x;
    float m = g_stats[c] / (float)NNODES;
    float v = g_stats[DHID + c] / (float)NNODES - m * m;
    float sc = g[c] * rsqrtf(v + BN_EPS);
    g_scale[c] = sc;
    g_shift[c] = be[c] - m * sc;
}

__global__ void bn_apply_relu_kernel(float* __restrict__ out) {
    int i = blockIdx.x * blockDim.x + threadIdx.x;
    if (i >= NNODES * DHID / 4) return;
    int c4 = (i % (DHID / 4)) * 4;
    float4 v  = *(const float4*)(g_pre + (size_t)i * 4);
    float4 sc = *(const float4*)(g_scale + c4);
    float4 sh = *(const float4*)(g_shift + c4);
    float4 o;
    o.x = fmaxf(v.x * sc.x + sh.x, 0.f);
    o.y = fmaxf(v.y * sc.y + sh.y, 0.f);
    o.z = fmaxf(v.z * sc.z + sh.z, 0.f);
    o.w = fmaxf(v.w * sc.w + sh.w, 0.f);
    *(float4*)(out + (size_t)i * 4) = o;
}

// ---------------- launch ------------------------------------------------------
extern "C" void kernel_launch(void* const* d_in, const int* in_sizes, int n_in,
                              void* d_out, int out_size) {
    const float* x    = (const float*)d_in[0];
    const int*   ei32 = (const int*)d_in[1];
    const float* ew   = (const float*)d_in[2];
    const float* W1   = (const float*)d_in[3];
    const float* b1   = (const float*)d_in[4];
    const float* W2   = (const float*)d_in[5];
    const float* b2   = (const float*)d_in[6];
    const float* W3   = (const float*)d_in[7];
    const float* b3   = (const float*)d_in[8];
    const float* g1   = (const float*)d_in[9];
    const float* be1  = (const float*)d_in[10];
    const float* g2   = (const float*)d_in[11];
    const float* be2  = (const float*)d_in[12];
    const float* pW1  = (const float*)d_in[13];
    const float* pb1  = (const float*)d_in[14];
    const float* pW2  = (const float*)d_in[15];
    const float* pb2  = (const float*)d_in[16];

    float* out_logits = (float*)d_out;                              // [N,64]
    float* out_h      = out_logits + (size_t)NNODES * DOUT;         // [N,128]
    float* out_z      = out_h      + (size_t)NNODES * DHID;         // [N,128]

    const int EB = (NEDGES + 255) / 256;
    const int PB = (NNODES * 32 + 255) / 256;     // warp per node
    const int AB = (NNODES * DHID / 4 + 255) / 256;
    const int GB = (NNODES + 127) / 128;

    const int SM128 = (2 * 128 * LDS_ + 2 * 128 * LDS_) * 2;   // 139264 B
    const int SM64  = (2 * 128 * LDS_ + 2 * 64  * LDS_) * 2;   // 104448 B
    cudaFuncSetAttribute((const void*)gemm_wmma_kernel<DHID, false, true>,
                         cudaFuncAttributeMaxDynamicSharedMemorySize, SM128);
    cudaFuncSetAttribute((const void*)gemm_wmma_kernel<DHID, true, true>,
                         cudaFuncAttributeMaxDynamicSharedMemorySize, SM128);
    cudaFuncSetAttribute((const void*)gemm_wmma_kernel<DOUT, false, false>,
                         cudaFuncAttributeMaxDynamicSharedMemorySize, SM64);

    // --- dtype detect + CSR build (parallel scan) ---
    detect_dtype_kernel<<<1, 1024>>>(ei32);
    zero_cursor_kernel<<<NB, 256>>>();
    hist_kernel<<<EB, 256>>>(ei32);
    block_reduce_kernel<<<NB, 256>>>();
    scan_bsums_kernel<<<1, 512>>>();
    block_scan_kernel<<<NB, 256>>>();
    scatter_kernel<<<EB, 256>>>(ei32, ew);

    // --- layer 1: propagate(x) @ W1.T + b1 -> bn stats ---
    propagate_kernel<false><<<PB, 256>>>(SEL_ARG, x);               // -> g_agg
    gemm_wmma_kernel<DHID, false, true><<<GB, 256, SM128>>>(
        SEL_AGG, nullptr, W1, b1, SEL_PRE, nullptr);
    zero_stats_kernel<<<1, 256>>>();
    bn_stats_kernel<<<256, DHID>>>();
    bn_finalize_kernel<<<1, DHID>>>(g1, be1);

    // --- layer 2: propagate(bn_relu(g_pre)) fused -> gemm -> bn ---
    propagate_kernel<true><<<PB, 256>>>(SEL_PRE, nullptr);          // -> g_agg
    gemm_wmma_kernel<DHID, false, true><<<GB, 256, SM128>>>(
        SEL_AGG, nullptr, W2, b2, SEL_PRE, nullptr);
    zero_stats_kernel<<<1, 256>>>();
    bn_stats_kernel<<<256, DHID>>>();
    bn_finalize_kernel<<<1, DHID>>>(g2, be2);
    bn_apply_relu_kernel<<<AB, 256>>>(out_h);                       // g_pre -> out_h

    // --- logits via linearity: t = out_h @ W3.T -> g_agg[N,64];
    //     logits = propagate64(t) + b3
    gemm_wmma_kernel<DOUT, false, false><<<GB, 256, SM64>>>(
        SEL_ARG, out_h, W3, b3, SEL_AGG, nullptr);
    propagate64_bias_kernel<<<PB, 256>>>(b3, out_logits);

    // --- proj head: z = relu(out_h @ pW1.T + pb1) @ pW2.T + pb2 -> out_z ---
    gemm_wmma_kernel<DHID, true, true><<<GB, 256, SM128>>>(
        SEL_ARG, out_h, pW1, pb1, SEL_PRE, nullptr);
    gemm_wmma_kernel<DHID, false, true><<<GB, 256, SM128>>>(
        SEL_PRE, nullptr, pW2, pb2, SEL_ARG, out_z);
}

// round 17
// speedup vs baseline: 1.0040x; 1.0040x over previous
#include <cuda_runtime.h>
#include <cuda_bf16.h>
#include <mma.h>
#include <math.h>

using namespace nvcuda;

#define NNODES 100000
#define NEDGES 1600000
#define DHID 128
#define DOUT 64
#define BN_EPS 1e-5f
#define NB ((NNODES + 255) / 256)
#define LDS_ 136   // smem row stride (bf16 elems) for 128-wide tiles

// buffer selectors
#define SEL_ARG 0
#define SEL_AGG 1
#define SEL_PRE 2

// ---------------- scratch (static device globals; no allocation) -------------
__device__ __align__(16) float g_agg[NNODES * DHID];
__device__ __align__(16) float g_pre[NNODES * DHID];
__device__ int   g_rowptr[NNODES + 1];
__device__ int   g_cursor[NNODES];
__device__ int   g_bsum[NB];
__device__ int   g_boff[NB];
__device__ int   g_srcs[NEDGES];
__device__ __align__(16) float g_wts [NEDGES];
__device__ float g_stats[2 * DHID];
__device__ __align__(16) float g_scale[DHID];
__device__ __align__(16) float g_shift[DHID];
__device__ int   g_is64;

__device__ __forceinline__ const float* sel_cbuf(int sel, const float* arg) {
    switch (sel) {
        case SEL_AGG: return g_agg;
        case SEL_PRE: return g_pre;
        default:      return arg;
    }
}
__device__ __forceinline__ float* sel_mbuf(int sel, float* arg) {
    switch (sel) {
        case SEL_AGG: return g_agg;
        case SEL_PRE: return g_pre;
        default:      return arg;
    }
}

__device__ __forceinline__ int fetch_src(const int* ei32, int e, int is64) {
    return is64 ? ei32[2 * e] : ei32[e];
}
__device__ __forceinline__ int fetch_dst(const int* ei32, int e, int is64) {
    return is64 ? ei32[2 * (NEDGES + e)] : ei32[NEDGES + e];
}

// split a float4 into bf16 hi/lo, packed stores
__device__ __forceinline__ void split_store4(__nv_bfloat16* hip,
                                             __nv_bfloat16* lop, float4 v) {
    float f[4] = {v.x, v.y, v.z, v.w};
    __nv_bfloat16 h[4], l[4];
    #pragma unroll
    for (int j = 0; j < 4; j++) {
        h[j] = __float2bfloat16(f[j]);
        l[j] = __float2bfloat16(f[j] - __bfloat162float(h[j]));
    }
    ((__nv_bfloat162*)hip)[0] = __nv_bfloat162(h[0], h[1]);
    ((__nv_bfloat162*)hip)[1] = __nv_bfloat162(h[2], h[3]);
    ((__nv_bfloat162*)lop)[0] = __nv_bfloat162(l[0], l[1]);
    ((__nv_bfloat162*)lop)[1] = __nv_bfloat162(l[2], l[3]);
}

// ---------------- dtype detection --------------------------------------------
__global__ void detect_dtype_kernel(const int* __restrict__ ei32) {
    __shared__ int s_nonzero;
    if (threadIdx.x == 0) s_nonzero = 0;
    __syncthreads();
    for (int k = threadIdx.x; k < 4096; k += blockDim.x) {
        if (ei32[2 * k + 1] != 0) atomicOr(&s_nonzero, 1);
    }
    __syncthreads();
    if (threadIdx.x == 0) g_is64 = s_nonzero ? 0 : 1;
}

// ---------------- small utility kernels --------------------------------------
__global__ void zero_cursor_kernel() {
    int i = blockIdx.x * blockDim.x + threadIdx.x;
    if (i < NNODES) g_cursor[i] = 0;
}
__global__ void zero_stats_kernel() {
    int i = threadIdx.x;
    if (i < 2 * DHID) g_stats[i] = 0.0f;
}

// ---------------- CSR build ---------------------------------------------------
__global__ void hist_kernel(const int* __restrict__ ei32) {
    int e = blockIdx.x * blockDim.x + threadIdx.x;
    if (e < NEDGES) {
        int d = fetch_dst(ei32, e, g_is64);
        atomicAdd(&g_cursor[d], 1);
    }
}

__global__ void block_reduce_kernel() {
    __shared__ int ws[8];
    int tid = threadIdx.x, lane = tid & 31, wid = tid >> 5;
    int i = blockIdx.x * 256 + tid;
    int v = (i < NNODES) ? g_cursor[i] : 0;
    #pragma unroll
    for (int d = 16; d > 0; d >>= 1) v += __shfl_down_sync(0xFFFFFFFFu, v, d);
    if (lane == 0) ws[wid] = v;
    __syncthreads();
    if (wid == 0) {
        int s = (lane < 8) ? ws[lane] : 0;
        #pragma unroll
        for (int d = 4; d > 0; d >>= 1) s += __shfl_down_sync(0xFFFFFFFFu, s, d);
        if (lane == 0) g_bsum[blockIdx.x] = s;
    }
}

__global__ void scan_bsums_kernel() {
    __shared__ int wsum[16];
    int tid = threadIdx.x, lane = tid & 31, wid = tid >> 5;
    int v = (tid < NB) ? g_bsum[tid] : 0;
    int x = v;
    #pragma unroll
    for (int d = 1; d < 32; d <<= 1) {
        int y = __shfl_up_sync(0xFFFFFFFFu, x, d);
        if (lane >= d) x += y;
    }
    if (lane == 31) wsum[wid] = x;
    __syncthreads();
    if (wid == 0) {
        int s = (lane < 16) ? wsum[lane] : 0;
        #pragma unroll
        for (int d = 1; d < 16; d <<= 1) {
            int y = __shfl_up_sync(0xFFFFFFFFu, s, d);
            if (lane >= d) s += y;
        }
        if (lane < 16) wsum[lane] = s;
    }
    __syncthreads();
    int incl = x + (wid > 0 ? wsum[wid - 1] : 0);
    if (tid < NB) g_boff[tid] = incl - v;
    if (tid == NB - 1) g_rowptr[NNODES] = incl;
}

__global__ void block_scan_kernel() {
    __shared__ int ws[8];
    int tid = threadIdx.x, lane = tid & 31, wid = tid >> 5;
    int i = blockIdx.x * 256 + tid;
    int v = (i < NNODES) ? g_cursor[i] : 0;
    int x = v;
    #pragma unroll
    for (int d = 1; d < 32; d <<= 1) {
        int y = __shfl_up_sync(0xFFFFFFFFu, x, d);
        if (lane >= d) x += y;
    }
    if (lane == 31) ws[wid] = x;
    __syncthreads();
    if (wid == 0 && lane < 8) {
        int s = ws[lane];
        #pragma unroll
        for (int d = 1; d < 8; d <<= 1) {
            int y = __shfl_up_sync(0x000000FFu, s, d);
            if (lane >= d) s += y;
        }
        ws[lane] = s;
    }
    __syncthreads();
    int excl = x - v + (wid > 0 ? ws[wid - 1] : 0) + g_boff[blockIdx.x];
    if (i < NNODES) { g_rowptr[i] = excl; g_cursor[i] = excl; }
}

__global__ void scatter_kernel(const int* __restrict__ ei32,
                               const float* __restrict__ ew) {
    int e = blockIdx.x * blockDim.x + threadIdx.x;
    if (e < NEDGES) {
        int is64 = g_is64;
        int s = fetch_src(ei32, e, is64);
        int d = fetch_dst(ei32, e, is64);
        float w = ew[e];
        int pos = atomicAdd(&g_cursor[d], 1);
        g_srcs[pos] = s;
        g_wts [pos] = w;
    }
}

// ---------------- propagate (128-dim): warp-per-node gather -> g_agg ----------
template <bool BN>
__global__ void propagate_kernel(int hsel, const float* __restrict__ harg) {
    const float* __restrict__ h = BN ? g_pre : sel_cbuf(hsel, harg);
    int warp = (blockIdx.x * blockDim.x + threadIdx.x) >> 5;
    int lane = threadIdx.x & 31;
    if (warp >= NNODES) return;
    float4 sc, sh;
    if (BN) {
        sc = ((const float4*)g_scale)[lane];
        sh = ((const float4*)g_shift)[lane];
    }
    int beg = g_rowptr[warp];
    int end = g_rowptr[warp + 1];
    float4 acc = make_float4(0.f, 0.f, 0.f, 0.f);
    for (int e = beg; e < end; e++) {
        int   s = g_srcs[e];
        float w = g_wts[e];
        float4 v = *((const float4*)(h + (size_t)s * DHID) + lane);
        if (BN) {
            v.x = fmaxf(v.x * sc.x + sh.x, 0.f);
            v.y = fmaxf(v.y * sc.y + sh.y, 0.f);
            v.z = fmaxf(v.z * sc.z + sh.z, 0.f);
            v.w = fmaxf(v.w * sc.w + sh.w, 0.f);
        }
        acc.x += w * v.x; acc.y += w * v.y;
        acc.z += w * v.z; acc.w += w * v.w;
    }
    ((float4*)(g_agg + (size_t)warp * DHID))[lane] = acc;
}

// ---------------- propagate (64-dim) + bias: logits path ----------------------
// out = sum_e w_e * g_agg[src_e] + b3  (g_agg holds out_h @ W3.T, 64-stride)
__global__ void propagate64_bias_kernel(const float* __restrict__ bias,
                                        float* __restrict__ out) {
    int warp = (blockIdx.x * blockDim.x + threadIdx.x) >> 5;
    int lane = threadIdx.x & 31;
    if (warp >= NNODES) return;
    int beg = g_rowptr[warp];
    int end = g_rowptr[warp + 1];
    float2 acc = make_float2(0.f, 0.f);
    for (int e = beg; e < end; e++) {
        int   s = g_srcs[e];
        float w = g_wts[e];
        float2 v = *((const float2*)(g_agg + (size_t)s * DOUT) + lane);
        acc.x += w * v.x; acc.y += w * v.y;
    }
    float2 b = ((const float2*)bias)[lane];
    acc.x += b.x; acc.y += b.y;
    ((float2*)(out + (size_t)warp * DOUT))[lane] = acc;
}

// ---------------- tensor-core GEMM: fully smem-resident K ---------------------
// C[N,NC] = A[N,128] @ W[NC,128]^T (+bias) (+relu)
template <int NC, bool RELU, bool BIAS>
__launch_bounds__(256)
__global__ void gemm_wmma_kernel(int asel, const float* __restrict__ Aarg,
                                 const float* __restrict__ W,
                                 const float* __restrict__ bias,
                                 int csel, float* __restrict__ Carg) {
    constexpr int BM = 128, K = 128;
    constexpr int NF = NC / 32;
    const float* __restrict__ A = sel_cbuf(asel, Aarg);
    float* __restrict__ C = sel_mbuf(csel, Carg);

    extern __shared__ __align__(16) char dsm[];
    __nv_bfloat16* sAh = (__nv_bfloat16*)dsm;           // [BM][LDS_]
    __nv_bfloat16* sAl = sAh + BM * LDS_;
    __nv_bfloat16* sWh = sAl + BM * LDS_;               // [NC][LDS_]
    __nv_bfloat16* sWl = sWh + NC * LDS_;
    float* Cs = (float*)dsm;                            // epilogue overlay

    int tid  = threadIdx.x;
    int row0 = blockIdx.x * BM;

    #pragma unroll
    for (int i = tid; i < BM * (K / 4); i += 256) {
        int r = i / (K / 4), c4 = (i % (K / 4)) * 4;
        int gr = row0 + r;
        float4 v = (gr < NNODES)
            ? *(const float4*)(A + (size_t)gr * K + c4)
            : make_float4(0.f, 0.f, 0.f, 0.f);
        split_store4(sAh + r * LDS_ + c4, sAl + r * LDS_ + c4, v);
    }
    #pragma unroll
    for (int i = tid; i < NC * (K / 4); i += 256) {
        int r = i / (K / 4), c4 = (i % (K / 4)) * 4;
        float4 v = *(const float4*)(W + (size_t)r * K + c4);
        split_store4(sWh + r * LDS_ + c4, sWl + r * LDS_ + c4, v);
    }
    __syncthreads();

    int wid = tid >> 5;
    int wr  = wid >> 1;
    int wc  = wid & 1;

    wmma::fragment<wmma::accumulator, 16, 16, 16, float> acc[2][NF];
    #pragma unroll
    for (int m = 0; m < 2; m++)
        #pragma unroll
        for (int n = 0; n < NF; n++) wmma::fill_fragment(acc[m][n], 0.f);

    #pragma unroll
    for (int k0 = 0; k0 < K; k0 += 16) {
        wmma::fragment<wmma::matrix_a, 16, 16, 16, __nv_bfloat16, wmma::row_major> ah[2], al[2];
        wmma::fragment<wmma::matrix_b, 16, 16, 16, __nv_bfloat16, wmma::col_major> bh[NF], bl[NF];
        #pragma unroll
        for (int m = 0; m < 2; m++) {
            int r = wr * 32 + m * 16;
            wmma::load_matrix_sync(ah[m], sAh + r * LDS_ + k0, LDS_);
            wmma::load_matrix_sync(al[m], sAl + r * LDS_ + k0, LDS_);
        }
        #pragma unroll
        for (int n = 0; n < NF; n++) {
            int c = wc * (NC / 2) + n * 16;
            wmma::load_matrix_sync(bh[n], sWh + c * LDS_ + k0, LDS_);
            wmma::load_matrix_sync(bl[n], sWl + c * LDS_ + k0, LDS_);
        }
        #pragma unroll
        for (int m = 0; m < 2; m++)
            #pragma unroll
            for (int n = 0; n < NF; n++) {
                wmma::mma_sync(acc[m][n], ah[m], bh[n], acc[m][n]);
                wmma::mma_sync(acc[m][n], ah[m], bl[n], acc[m][n]);
                wmma::mma_sync(acc[m][n], al[m], bh[n], acc[m][n]);
            }
    }

    __syncthreads();
    #pragma unroll
    for (int m = 0; m < 2; m++)
        #pragma unroll
        for (int n = 0; n < NF; n++)
            wmma::store_matrix_sync(
                Cs + (wr * 32 + m * 16) * NC + wc * (NC / 2) + n * 16,
                acc[m][n], NC, wmma::mem_row_major);
    __syncthreads();
    #pragma unroll
    for (int i = tid; i < BM * (NC / 4); i += 256) {
        int r = i / (NC / 4), c4 = (i % (NC / 4)) * 4;
        int gr = row0 + r;
        if (gr < NNODES) {
            float4 v = *(float4*)(Cs + r * NC + c4);
            float4 o = v;
            if (BIAS) {
                float4 b = *(const float4*)(bias + c4);
                o.x += b.x; o.y += b.y; o.z += b.z; o.w += b.w;
            }
            if (RELU) {
                o.x = fmaxf(o.x, 0.f); o.y = fmaxf(o.y, 0.f);
                o.z = fmaxf(o.z, 0.f); o.w = fmaxf(o.w, 0.f);
            }
            *(float4*)(C + (size_t)gr * NC + c4) = o;
        }
    }
}

// ---------------- BatchNorm (stats over g_pre) --------------------------------
__global__ void bn_stats_kernel() {
    int c = threadIdx.x;
    float s = 0.f, sq = 0.f;
    for (int r = blockIdx.x; r < NNODES; r += gridDim.x) {
        float v = g_pre[(size_t)r * DHID + c];
        s += v; sq += v * v;
    }
    atomicAdd(&g_stats[c], s);
    atomicAdd(&g_stats[DHID + c], sq);
}

__global__ void bn_finalize_kernel(const float* __restrict__ g,
                                   const float* __restrict__ be) {
    int c = threadIdx.x;
    float m = g_stats[c] / (float)NNODES;
    float v = g_stats[DHID + c] / (float)NNODES - m * m;
    float sc = g[c] * rsqrtf(v + BN_EPS);
    g_scale[c] = sc;
    g_shift[c] = be[c] - m * sc;
}

__global__ void bn_apply_relu_kernel(float* __restrict__ out) {
    int i = blockIdx.x * blockDim.x + threadIdx.x;
    if (i >= NNODES * DHID / 4) return;
    int c4 = (i % (DHID / 4)) * 4;
    float4 v  = *(const float4*)(g_pre + (size_t)i * 4);
    float4 sc = *(const float4*)(g_scale + c4);
    float4 sh = *(const float4*)(g_shift + c4);
    float4 o;
    o.x = fmaxf(v.x * sc.x + sh.x, 0.f);
    o.y = fmaxf(v.y * sc.y + sh.y, 0.f);
    o.z = fmaxf(v.z * sc.z + sh.z, 0.f);
    o.w = fmaxf(v.w * sc.w + sh.w, 0.f);
    *(float4*)(out + (size_t)i * 4) = o;
}

// ---------------- launch ------------------------------------------------------
extern "C" void kernel_launch(void* const* d_in, const int* in_sizes, int n_in,
                              void* d_out, int out_size) {
    const float* x    = (const float*)d_in[0];
    const int*   ei32 = (const int*)d_in[1];
    const float* ew   = (const float*)d_in[2];
    const float* W1   = (const float*)d_in[3];
    const float* b1   = (const float*)d_in[4];
    const float* W2   = (const float*)d_in[5];
    const float* b2   = (const float*)d_in[6];
    const float* W3   = (const float*)d_in[7];
    const float* b3   = (const float*)d_in[8];
    const float* g1   = (const float*)d_in[9];
    const float* be1  = (const float*)d_in[10];
    const float* g2   = (const float*)d_in[11];
    const float* be2  = (const float*)d_in[12];
    const float* pW1  = (const float*)d_in[13];
    const float* pb1  = (const float*)d_in[14];
    const float* pW2  = (const float*)d_in[15];
    const float* pb2  = (const float*)d_in[16];

    float* out_logits = (float*)d_out;                              // [N,64]
    float* out_h      = out_logits + (size_t)NNODES * DOUT;         // [N,128]
    float* out_z      = out_h      + (size_t)NNODES * DHID;         // [N,128]

    const int EB = (NEDGES + 255) / 256;
    const int PB = (NNODES * 32 + 255) / 256;     // warp per node
    const int AB = (NNODES * DHID / 4 + 255) / 256;
    const int GB = (NNODES + 127) / 128;

    const int SM128 = (2 * 128 * LDS_ + 2 * 128 * LDS_) * 2;   // 139264 B
    const int SM64  = (2 * 128 * LDS_ + 2 * 64  * LDS_) * 2;   // 104448 B
    cudaFuncSetAttribute((const void*)gemm_wmma_kernel<DHID, false, true>,
                         cudaFuncAttributeMaxDynamicSharedMemorySize, SM128);
    cudaFuncSetAttribute((const void*)gemm_wmma_kernel<DHID, true, true>,
                         cudaFuncAttributeMaxDynamicSharedMemorySize, SM128);
    cudaFuncSetAttribute((const void*)gemm_wmma_kernel<DOUT, false, false>,
                         cudaFuncAttributeMaxDynamicSharedMemorySize, SM64);

    // --- dtype detect + CSR build (parallel scan) ---
    detect_dtype_kernel<<<1, 1024>>>(ei32);
    zero_cursor_kernel<<<NB, 256>>>();
    hist_kernel<<<EB, 256>>>(ei32);
    block_reduce_kernel<<<NB, 256>>>();
    scan_bsums_kernel<<<1, 512>>>();
    block_scan_kernel<<<NB, 256>>>();
    scatter_kernel<<<EB, 256>>>(ei32, ew);

    // --- layer 1: propagate(x) @ W1.T + b1 -> bn stats ---
    propagate_kernel<false><<<PB, 256>>>(SEL_ARG, x);               // -> g_agg
    gemm_wmma_kernel<DHID, false, true><<<GB, 256, SM128>>>(
        SEL_AGG, nullptr, W1, b1, SEL_PRE, nullptr);
    zero_stats_kernel<<<1, 256>>>();
    bn_stats_kernel<<<256, DHID>>>();
    bn_finalize_kernel<<<1, DHID>>>(g1, be1);

    // --- layer 2: propagate(bn_relu(g_pre)) fused -> gemm -> bn ---
    propagate_kernel<true><<<PB, 256>>>(SEL_PRE, nullptr);          // -> g_agg
    gemm_wmma_kernel<DHID, false, true><<<GB, 256, SM128>>>(
        SEL_AGG, nullptr, W2, b2, SEL_PRE, nullptr);
    zero_stats_kernel<<<1, 256>>>();
    bn_stats_kernel<<<256, DHID>>>();
    bn_finalize_kernel<<<1, DHID>>>(g2, be2);
    bn_apply_relu_kernel<<<AB, 256>>>(out_h);                       // g_pre -> out_h

    // --- logits via linearity: t = out_h @ W3.T -> g_agg[N,64];
    //     logits = propagate64(t) + b3
    gemm_wmma_kernel<DOUT, false, false><<<GB, 256, SM64>>>(
        SEL_ARG, out_h, W3, b3, SEL_AGG, nullptr);
    propagate64_bias_kernel<<<PB, 256>>>(b3, out_logits);

    // --- proj head: z = relu(out_h @ pW1.T + pb1) @ pW2.T + pb2 -> out_z ---
    gemm_wmma_kernel<DHID, true, true><<<GB, 256, SM128>>>(
        SEL_ARG, out_h, pW1, pb1, SEL_PRE, nullptr);
    gemm_wmma_kernel<DHID, false, true><<<GB, 256, SM128>>>(
        SEL_PRE, nullptr, pW2, pb2, SEL_ARG, out_z);
}